// round 1
// baseline (speedup 1.0000x reference)
#include <cuda_runtime.h>
#include <math.h>

#define LSEQ 2048
#define DM   768
#define DI   1536
#define RK   48
#define DS   16
#define NCH  64     // number of chunks
#define CLEN 32     // chunk length (NCH*CLEN == LSEQ)

// -------- static scratch (allocation-free) --------
__device__ float g_xr[LSEQ * 2 * DI];      // in_proj output [L, 3072]
__device__ float g_u[LSEQ * DI];           // conv+silu output
__device__ float g_delta[LSEQ * DI];       // softplus(dt)
__device__ float g_xdbl[LSEQ * 80];        // x_proj output [L, 80]
__device__ float g_y[LSEQ * DI];           // scan output * silu(res)
__device__ float g_hc[NCH * DI * DS];      // chunk end states -> chunk init states
__device__ float g_send[NCH * DI];         // per-chunk sum of delta

// ============================================================
// Generic SIMT fp32 GEMM: C[M,N] = A[M,K] @ B[K,N]
// BM=BN=128, BK=8, 256 threads, 8x8 per-thread micro-tile.
// EPI: 0 = plain store, 1 = softplus(acc + bias[col])
// Requires: M%128==0, K%8==0, lda/ldb/ldc %4==0. N arbitrary (guarded).
// ============================================================
template <int EPI>
__launch_bounds__(256)
__global__ void sgemm(const float* __restrict__ A, const float* __restrict__ B,
                      float* __restrict__ C, int M, int N, int K,
                      int lda, int ldb, int ldc, const float* __restrict__ bias)
{
    __shared__ __align__(16) float As[8][128];
    __shared__ __align__(16) float Bs[8][128];

    const int tid = threadIdx.x;
    const int bm = blockIdx.y * 128;
    const int bn = blockIdx.x * 128;

    // A tile loader: 128 rows x 8 cols, float4 per thread
    const int arow = tid >> 1;
    const int acol = (tid & 1) * 4;
    // B tile loader: 8 rows x 128 cols, float4 per thread
    const int brow = tid >> 5;
    const int bcol = (tid & 31) * 4;

    const int tr = (tid >> 4) * 8;   // thread row within tile
    const int tc = (tid & 15) * 8;   // thread col within tile

    float acc[8][8];
#pragma unroll
    for (int i = 0; i < 8; i++)
#pragma unroll
        for (int j = 0; j < 8; j++) acc[i][j] = 0.f;

    for (int k0 = 0; k0 < K; k0 += 8) {
        // ---- load A tile (always in-bounds: M%128==0, K%8==0) ----
        {
            const float4 a = *reinterpret_cast<const float4*>(
                &A[(size_t)(bm + arow) * lda + k0 + acol]);
            As[acol + 0][arow] = a.x;
            As[acol + 1][arow] = a.y;
            As[acol + 2][arow] = a.z;
            As[acol + 3][arow] = a.w;
        }
        // ---- load B tile (guard N) ----
        {
            const int col = bn + bcol;
            if (col + 3 < N) {
                *reinterpret_cast<float4*>(&Bs[brow][bcol]) =
                    *reinterpret_cast<const float4*>(&B[(size_t)(k0 + brow) * ldb + col]);
            } else {
#pragma unroll
                for (int j = 0; j < 4; j++)
                    Bs[brow][bcol + j] =
                        (col + j < N) ? B[(size_t)(k0 + brow) * ldb + col + j] : 0.f;
            }
        }
        __syncthreads();

#pragma unroll
        for (int kk = 0; kk < 8; kk++) {
            float4 a0 = *reinterpret_cast<const float4*>(&As[kk][tr]);
            float4 a1 = *reinterpret_cast<const float4*>(&As[kk][tr + 4]);
            float4 b0 = *reinterpret_cast<const float4*>(&Bs[kk][tc]);
            float4 b1 = *reinterpret_cast<const float4*>(&Bs[kk][tc + 4]);
            float af[8] = {a0.x, a0.y, a0.z, a0.w, a1.x, a1.y, a1.z, a1.w};
            float bf[8] = {b0.x, b0.y, b0.z, b0.w, b1.x, b1.y, b1.z, b1.w};
#pragma unroll
            for (int i = 0; i < 8; i++)
#pragma unroll
                for (int j = 0; j < 8; j++)
                    acc[i][j] = fmaf(af[i], bf[j], acc[i][j]);
        }
        __syncthreads();
    }

#pragma unroll
    for (int i = 0; i < 8; i++) {
        const int row = bm + tr + i;
#pragma unroll
        for (int j = 0; j < 8; j++) {
            const int col = bn + tc + j;
            if (col < N) {
                float v = acc[i][j];
                if (EPI == 1) {
                    v = v + bias[col];
                    // numerically stable softplus
                    v = fmaxf(v, 0.f) + log1pf(__expf(-fabsf(v)));
                }
                C[(size_t)row * ldc + col] = v;
            }
        }
    }
}

// ============================================================
// depthwise causal conv (width 4) + bias + SiLU
// reads g_xr[:, 0:DI], writes g_u
// ============================================================
__global__ void conv_silu_kernel(const float* __restrict__ cw,
                                 const float* __restrict__ cb)
{
    const int idx = blockIdx.x * blockDim.x + threadIdx.x; // over L*DI
    const int d = idx % DI;
    const int t = idx / DI;
    float acc = cb[d];
#pragma unroll
    for (int k = 0; k < 4; k++) {
        const int tt = t - 3 + k;
        if (tt >= 0) acc = fmaf(g_xr[(size_t)tt * (2 * DI) + d], cw[k * DI + d], acc);
    }
    g_u[idx] = acc / (1.f + __expf(-acc));   // silu
}

// ============================================================
// scan phase 1: per (chunk, d) run local recurrence from zero state;
// store chunk-end states + sum(delta) over the chunk.
// ============================================================
__global__ void scan_phase1(const float* __restrict__ a_log)
{
    const int c = blockIdx.y;
    const int d = blockIdx.x * 256 + threadIdx.x;
    __shared__ float bs[CLEN][DS];
    for (int i = threadIdx.x; i < CLEN * DS; i += 256) {
        const int t = i / DS, n = i % DS;
        bs[t][n] = g_xdbl[(size_t)(c * CLEN + t) * 80 + RK + n];
    }
    __syncthreads();

    float an[DS];
#pragma unroll
    for (int n = 0; n < DS; n++) an[n] = -__expf(a_log[d * DS + n]);

    float h[DS];
#pragma unroll
    for (int n = 0; n < DS; n++) h[n] = 0.f;
    float s = 0.f;

    for (int t = 0; t < CLEN; t++) {
        const int row = c * CLEN + t;
        const float dl = g_delta[(size_t)row * DI + d];
        const float uv = g_u[(size_t)row * DI + d];
        const float du = dl * uv;
        s += dl;
#pragma unroll
        for (int n = 0; n < DS; n++) {
            const float e = __expf(dl * an[n]);
            h[n] = fmaf(e, h[n], du * bs[t][n]);
        }
    }
    g_send[c * DI + d] = s;
#pragma unroll
    for (int n = 0; n < DS; n++) g_hc[((size_t)c * DI + d) * DS + n] = h[n];
}

// ============================================================
// scan phase 2: sequential over chunks; converts g_hc from
// "local end state" to "true initial state of chunk".
// one thread per (d, n)
// ============================================================
__global__ void scan_phase2(const float* __restrict__ a_log)
{
    const int gid = blockIdx.x * 256 + threadIdx.x;  // 0..DI*DS-1
    const int d = gid / DS;
    const float an = -__expf(a_log[gid]);            // a_log[d*DS+n] == a_log[gid]
    float H = 0.f;
    for (int c = 0; c < NCH; c++) {
        const float P = __expf(an * g_send[c * DI + d]);
        const size_t off = ((size_t)c * DI + d) * DS + (gid % DS);
        const float tmp = g_hc[off];
        g_hc[off] = H;                 // initial state for chunk c
        H = fmaf(P, H, tmp);           // true end state of chunk c
    }
}

// ============================================================
// scan phase 3: replay chunk with true initial state; emit
// y = (sum_n h*c + u*D) * silu(res)  ->  g_y
// ============================================================
__global__ void scan_phase3(const float* __restrict__ a_log,
                            const float* __restrict__ dpar)
{
    const int c = blockIdx.y;
    const int d = blockIdx.x * 256 + threadIdx.x;
    __shared__ float bs[CLEN][DS];
    __shared__ float cs[CLEN][DS];
    for (int i = threadIdx.x; i < CLEN * DS; i += 256) {
        const int t = i / DS, n = i % DS;
        bs[t][n] = g_xdbl[(size_t)(c * CLEN + t) * 80 + RK + n];
        cs[t][n] = g_xdbl[(size_t)(c * CLEN + t) * 80 + RK + DS + n];
    }
    __syncthreads();

    float an[DS];
#pragma unroll
    for (int n = 0; n < DS; n++) an[n] = -__expf(a_log[d * DS + n]);
    float h[DS];
#pragma unroll
    for (int n = 0; n < DS; n++) h[n] = g_hc[((size_t)c * DI + d) * DS + n];
    const float Dp = dpar[d];

    for (int t = 0; t < CLEN; t++) {
        const int row = c * CLEN + t;
        const float dl = g_delta[(size_t)row * DI + d];
        const float uv = g_u[(size_t)row * DI + d];
        const float du = dl * uv;
        float y = 0.f;
#pragma unroll
        for (int n = 0; n < DS; n++) {
            const float e = __expf(dl * an[n]);
            h[n] = fmaf(e, h[n], du * bs[t][n]);
            y = fmaf(h[n], cs[t][n], y);
        }
        y = fmaf(uv, Dp, y);
        const float r = g_xr[(size_t)row * (2 * DI) + DI + d];
        const float sr = r / (1.f + __expf(-r));  // silu(res)
        g_y[(size_t)row * DI + d] = y * sr;
    }
}

// ============================================================
// launch
// ============================================================
extern "C" void kernel_launch(void* const* d_in, const int* in_sizes, int n_in,
                              void* d_out, int out_size)
{
    const float* x         = (const float*)d_in[0];
    const float* in_proj_w = (const float*)d_in[1];
    const float* conv_w    = (const float*)d_in[2];
    const float* conv_b    = (const float*)d_in[3];
    const float* x_proj_w  = (const float*)d_in[4];
    const float* dt_proj_w = (const float*)d_in[5];
    const float* dt_proj_b = (const float*)d_in[6];
    const float* a_log     = (const float*)d_in[7];
    const float* d_param   = (const float*)d_in[8];
    const float* out_proj_w= (const float*)d_in[9];
    float* out = (float*)d_out;

    float *xr, *u, *delta, *xdbl, *y;
    cudaGetSymbolAddress((void**)&xr,    g_xr);
    cudaGetSymbolAddress((void**)&u,     g_u);
    cudaGetSymbolAddress((void**)&delta, g_delta);
    cudaGetSymbolAddress((void**)&xdbl,  g_xdbl);
    cudaGetSymbolAddress((void**)&y,     g_y);

    // GEMM1: x[2048,768] @ in_proj_w[768,3072] -> xr[2048,3072]
    sgemm<0><<<dim3((2 * DI) / 128, LSEQ / 128), 256>>>(
        x, in_proj_w, xr, LSEQ, 2 * DI, DM, DM, 2 * DI, 2 * DI, nullptr);

    // conv + silu -> u
    conv_silu_kernel<<<(LSEQ * DI) / 256, 256>>>(conv_w, conv_b);

    // GEMM2: u[2048,1536] @ x_proj_w[1536,80] -> xdbl[2048,80]
    sgemm<0><<<dim3(1, LSEQ / 128), 256>>>(
        u, x_proj_w, xdbl, LSEQ, 80, DI, DI, 80, 80, nullptr);

    // GEMM3: xdbl[:, :48] @ dt_proj_w[48,1536] + bias -> softplus -> delta
    sgemm<1><<<dim3(DI / 128, LSEQ / 128), 256>>>(
        xdbl, dt_proj_w, delta, LSEQ, DI, RK, 80, DI, DI, dt_proj_b);

    // chunked selective scan
    scan_phase1<<<dim3(DI / 256, NCH), 256>>>(a_log);
    scan_phase2<<<(DI * DS) / 256, 256>>>(a_log);
    scan_phase3<<<dim3(DI / 256, NCH), 256>>>(a_log, d_param);

    // GEMM4: y[2048,1536] @ out_proj_w[1536,768] -> out[2048,768]
    sgemm<0><<<dim3(DM / 128, LSEQ / 128), 256>>>(
        y, out_proj_w, out, LSEQ, DM, DI, DI, DM, DM, nullptr);
}

// round 5
// speedup vs baseline: 2.6673x; 2.6673x over previous
#include <cuda_runtime.h>
#include <cuda_bf16.h>
#include <math.h>
#include <stdint.h>

#define LSEQ 2048
#define DM   768
#define DI   1536
#define RK   48
#define DS   16
#define NCH  64
#define CLEN 32
#define KSPL 8      // K-split factor for GEMM2

// ---------------- static scratch ----------------
__device__ float g_xr[LSEQ * 2 * DI];
__device__ float g_u[LSEQ * DI];
__device__ float g_delta[LSEQ * DI];
__device__ float g_xdbl[LSEQ * 80];
__device__ float g_x2p[KSPL * LSEQ * 80];   // GEMM2 split-K partials
__device__ float g_hc[NCH * DI * DS];
__device__ float g_send[NCH * DI];

// bf16 hi/lo operands (plain row-major; B pre-transposed to [N,K])
__device__ __align__(16) __nv_bfloat16 g_a1hi[LSEQ * DM];
__device__ __align__(16) __nv_bfloat16 g_a1lo[LSEQ * DM];
__device__ __align__(16) __nv_bfloat16 g_b1hi[(2*DI) * DM];
__device__ __align__(16) __nv_bfloat16 g_b1lo[(2*DI) * DM];
__device__ __align__(16) __nv_bfloat16 g_a4hi[LSEQ * DI];
__device__ __align__(16) __nv_bfloat16 g_a4lo[LSEQ * DI];
__device__ __align__(16) __nv_bfloat16 g_b4hi[DM * DI];
__device__ __align__(16) __nv_bfloat16 g_b4lo[DM * DI];

// ---------------- helpers ----------------
__device__ __forceinline__ uint32_t smem_u32(const void* p) {
    uint32_t a;
    asm("{ .reg .u64 t; cvta.to.shared.u64 t, %1; cvt.u32.u64 %0, t; }" : "=r"(a) : "l"(p));
    return a;
}

__device__ __forceinline__ void cp16(uint32_t dst, const void* src) {
    asm volatile("cp.async.cg.shared.global [%0], [%1], 16;" :: "r"(dst), "l"(src) : "memory");
}
__device__ __forceinline__ void cp_commit() { asm volatile("cp.async.commit_group;" ::: "memory"); }
__device__ __forceinline__ void cp_wait2()  { asm volatile("cp.async.wait_group 2;" ::: "memory"); }

__device__ __forceinline__ void ldsm4(uint32_t* r, uint32_t addr) {
    asm volatile("ldmatrix.sync.aligned.m8n8.x4.shared.b16 {%0,%1,%2,%3}, [%4];"
                 : "=r"(r[0]), "=r"(r[1]), "=r"(r[2]), "=r"(r[3]) : "r"(addr));
}

__device__ __forceinline__ void mma16816(float* c, const uint32_t* a, const uint32_t* b) {
    asm volatile("mma.sync.aligned.m16n8k16.row.col.f32.bf16.bf16.f32 "
                 "{%0,%1,%2,%3}, {%4,%5,%6,%7}, {%8,%9}, {%0,%1,%2,%3};"
                 : "+f"(c[0]), "+f"(c[1]), "+f"(c[2]), "+f"(c[3])
                 : "r"(a[0]), "r"(a[1]), "r"(a[2]), "r"(a[3]), "r"(b[0]), "r"(b[1]));
}

// conflict-free swizzle for [row][32 bf16] tiles (64B rows, 16B chunks)
__device__ __forceinline__ uint32_t soff(int r, int c) {
    return (uint32_t)(r * 64 + ((c ^ ((r >> 1) & 3)) << 4));
}

// ============================================================
// bf16 tensor-core GEMM: C[M,N] = A@B^T(stored [N,K]), 3x split.
// Tile 128x128x32, 256 threads, 3-stage cp.async pipeline.
// M%128==0, N%128==0, K%32==0.
// ============================================================
__global__ __launch_bounds__(256, 1)
void hgemm(const __nv_bfloat16* __restrict__ Ahi, const __nv_bfloat16* __restrict__ Alo,
           const __nv_bfloat16* __restrict__ Bhi, const __nv_bfloat16* __restrict__ Blo,
           float* __restrict__ C, int M, int N, int K)
{
    extern __shared__ __align__(128) char smem[];
    const uint32_t sb = smem_u32(smem);
    const int tid = threadIdx.x;
    const int w   = tid >> 5, lid = tid & 31;
    const int wm  = (w >> 2) * 64;      // warp M offset (2 warps)
    const int wn  = (w & 3) * 32;       // warp N offset (4 warps)
    const int bm  = blockIdx.y * 128, bn = blockIdx.x * 128;
    const int KT  = K >> 5;

    // per-thread cp.async assignment: row = tid>>1, chunks (tid&1)*2 + {0,1}
    const int prow = tid >> 1;
    const int pc0  = (tid & 1) * 2;

    const __nv_bfloat16* gA[2] = {Ahi, Alo};
    const __nv_bfloat16* gB[2] = {Bhi, Blo};

    auto prefetch = [&](int kt) {
        const int s = kt % 3;
        const uint32_t st = sb + s * 32768;
        const int k0 = kt * 32;
#pragma unroll
        for (int hb = 0; hb < 2; hb++) {
            const __nv_bfloat16* srcA = gA[hb] + (size_t)(bm + prow) * K + k0;
            const __nv_bfloat16* srcB = gB[hb] + (size_t)(bn + prow) * K + k0;
            const uint32_t dA = st + hb * 8192;
            const uint32_t dB = st + 16384 + hb * 8192;
#pragma unroll
            for (int cc = 0; cc < 2; cc++) {
                const int c = pc0 + cc;
                cp16(dA + soff(prow, c), srcA + c * 8);
                cp16(dB + soff(prow, c), srcB + c * 8);
            }
        }
    };

    float acc[4][4][4];
#pragma unroll
    for (int i = 0; i < 4; i++)
#pragma unroll
        for (int j = 0; j < 4; j++)
#pragma unroll
            for (int e = 0; e < 4; e++) acc[i][j][e] = 0.f;

    prefetch(0); cp_commit();
    if (KT > 1) { prefetch(1); } cp_commit();
    if (KT > 2) { prefetch(2); } cp_commit();

    // ldmatrix lane geometry (constant per thread)
    const int lrA = ((lid >> 3) & 1) * 8 + (lid & 7);
    const int lhA = (lid >> 4) & 1;          // k-half for A
    const int jB  = lid >> 3;
    const int lrB = ((jB >> 1) & 1) * 8 + (lid & 7);
    const int lhB = jB & 1;                  // k-half for B

    for (int kt = 0; kt < KT; kt++) {
        cp_wait2();
        __syncthreads();
        const uint32_t st = sb + (kt % 3) * 32768;
#pragma unroll
        for (int ks = 0; ks < 2; ks++) {
            uint32_t ah[4][4], al[4][4], bh[2][4], bl[2][4];
            const int cA = ks * 2 + lhA;
            const int cB = ks * 2 + lhB;
#pragma unroll
            for (int mi = 0; mi < 4; mi++) {
                const uint32_t ad = st + soff(wm + mi * 16 + lrA, cA);
                ldsm4(ah[mi], ad);
                ldsm4(al[mi], ad + 8192);
            }
#pragma unroll
            for (int nf2 = 0; nf2 < 2; nf2++) {
                const uint32_t bd = st + 16384 + soff(wn + nf2 * 16 + lrB, cB);
                ldsm4(bh[nf2], bd);
                ldsm4(bl[nf2], bd + 8192);
            }
#pragma unroll
            for (int mi = 0; mi < 4; mi++) {
#pragma unroll
                for (int nf = 0; nf < 4; nf++) {
                    float* c = acc[mi][nf];
                    const uint32_t* B1 = &bh[nf >> 1][(nf & 1) * 2];
                    const uint32_t* B2 = &bl[nf >> 1][(nf & 1) * 2];
                    mma16816(c, ah[mi], B1);
                    mma16816(c, ah[mi], B2);
                    mma16816(c, al[mi], B1);
                }
            }
        }
        __syncthreads();
        if (kt + 3 < KT) prefetch(kt + 3);
        cp_commit();
    }

    // epilogue: lane holds (g,2t) pairs
    const int g = lid >> 2, t2 = (lid & 3) * 2;
#pragma unroll
    for (int mi = 0; mi < 4; mi++) {
        const int row0 = bm + wm + mi * 16 + g;
#pragma unroll
        for (int nf = 0; nf < 4; nf++) {
            const int col = bn + wn + nf * 8 + t2;
            float2 v0 = {acc[mi][nf][0], acc[mi][nf][1]};
            float2 v1 = {acc[mi][nf][2], acc[mi][nf][3]};
            *reinterpret_cast<float2*>(&C[(size_t)row0 * N + col]) = v0;
            *reinterpret_cast<float2*>(&C[(size_t)(row0 + 8) * N + col]) = v1;
        }
    }
}

// ============================================================
// conversions
// ============================================================
__global__ void convA(const float* __restrict__ src, __nv_bfloat16* __restrict__ hi,
                      __nv_bfloat16* __restrict__ lo, int total)
{
    const int idx = blockIdx.x * 256 + threadIdx.x;
    if (idx >= total) return;
    const float v = src[idx];
    const __nv_bfloat16 h = __float2bfloat16(v);
    hi[idx] = h;
    lo[idx] = __float2bfloat16(v - __bfloat162float(h));
}

// transpose+convert: src[K,N] fp32 -> hi/lo [N,K] bf16
__global__ void convBT(const float* __restrict__ src, __nv_bfloat16* __restrict__ hi,
                       __nv_bfloat16* __restrict__ lo, int K, int N)
{
    __shared__ float s[32][33];
    const int k0 = blockIdx.x * 32, n0 = blockIdx.y * 32;
    const int tx = threadIdx.x & 31, ty = threadIdx.x >> 5;
#pragma unroll
    for (int i = 0; i < 4; i++) {
        const int kr = i * 8 + ty;
        s[kr][tx] = src[(size_t)(k0 + kr) * N + n0 + tx];
    }
    __syncthreads();
#pragma unroll
    for (int i = 0; i < 4; i++) {
        const int nl = i * 8 + ty;
        const int n = n0 + nl, k = k0 + tx;
        const float v = s[tx][nl];
        const __nv_bfloat16 h = __float2bfloat16(v);
        const size_t o = (size_t)n * K + k;
        hi[o] = h;
        lo[o] = __float2bfloat16(v - __bfloat162float(h));
    }
}

// ============================================================
// SIMT fp32 GEMM (small GEMMs 2 & 3).
// gridDim.z > 1 => split-K: block z computes K-chunk z into partial
// buffer layer z (C + z*M*ldc). EPI must be 0 when split.
// ============================================================
template <int EPI>
__launch_bounds__(256)
__global__ void sgemm(const float* __restrict__ A, const float* __restrict__ B,
                      float* __restrict__ C, int M, int N, int K,
                      int lda, int ldb, int ldc, const float* __restrict__ bias)
{
    __shared__ __align__(16) float As[8][128];
    __shared__ __align__(16) float Bs[8][128];
    const int tid = threadIdx.x;
    const int bm = blockIdx.y * 128, bn = blockIdx.x * 128;
    const int arow = tid >> 1, acol = (tid & 1) * 4;
    const int brow = tid >> 5, bcol = (tid & 31) * 4;
    const int tr = (tid >> 4) * 8, tc = (tid & 15) * 8;

    // split-K range
    const int Kc = K / gridDim.z;
    const int kbeg = blockIdx.z * Kc;
    const int kend = kbeg + Kc;
    C += (size_t)blockIdx.z * M * ldc;

    float acc[8][8];
#pragma unroll
    for (int i = 0; i < 8; i++)
#pragma unroll
        for (int j = 0; j < 8; j++) acc[i][j] = 0.f;

    for (int k0 = kbeg; k0 < kend; k0 += 8) {
        {
            const float4 a = *reinterpret_cast<const float4*>(&A[(size_t)(bm + arow) * lda + k0 + acol]);
            As[acol + 0][arow] = a.x; As[acol + 1][arow] = a.y;
            As[acol + 2][arow] = a.z; As[acol + 3][arow] = a.w;
        }
        {
            const int col = bn + bcol;
            if (col + 3 < N) {
                *reinterpret_cast<float4*>(&Bs[brow][bcol]) =
                    *reinterpret_cast<const float4*>(&B[(size_t)(k0 + brow) * ldb + col]);
            } else {
#pragma unroll
                for (int j = 0; j < 4; j++)
                    Bs[brow][bcol + j] = (col + j < N) ? B[(size_t)(k0 + brow) * ldb + col + j] : 0.f;
            }
        }
        __syncthreads();
#pragma unroll
        for (int kk = 0; kk < 8; kk++) {
            float4 a0 = *reinterpret_cast<const float4*>(&As[kk][tr]);
            float4 a1 = *reinterpret_cast<const float4*>(&As[kk][tr + 4]);
            float4 b0 = *reinterpret_cast<const float4*>(&Bs[kk][tc]);
            float4 b1 = *reinterpret_cast<const float4*>(&Bs[kk][tc + 4]);
            float af[8] = {a0.x, a0.y, a0.z, a0.w, a1.x, a1.y, a1.z, a1.w};
            float bf[8] = {b0.x, b0.y, b0.z, b0.w, b1.x, b1.y, b1.z, b1.w};
#pragma unroll
            for (int i = 0; i < 8; i++)
#pragma unroll
                for (int j = 0; j < 8; j++) acc[i][j] = fmaf(af[i], bf[j], acc[i][j]);
        }
        __syncthreads();
    }
#pragma unroll
    for (int i = 0; i < 8; i++) {
        const int row = bm + tr + i;
#pragma unroll
        for (int j = 0; j < 8; j++) {
            const int col = bn + tc + j;
            if (col < N) {
                float v = acc[i][j];
                if (EPI == 1) {
                    v = v + bias[col];
                    v = fmaxf(v, 0.f) + log1pf(__expf(-fabsf(v)));
                }
                C[(size_t)row * ldc + col] = v;
            }
        }
    }
}

// reduce KSPL split-K partial layers -> final
__global__ void reduce_splitk(const float* __restrict__ p, float* __restrict__ o, int n)
{
    const int i = blockIdx.x * 256 + threadIdx.x;
    if (i >= n) return;
    float s = 0.f;
#pragma unroll
    for (int z = 0; z < KSPL; z++) s += p[(size_t)z * n + i];
    o[i] = s;
}

// ============================================================
// conv + silu
// ============================================================
__global__ void conv_silu_kernel(const float* __restrict__ cw, const float* __restrict__ cb)
{
    const int idx = blockIdx.x * blockDim.x + threadIdx.x;
    const int d = idx % DI, t = idx / DI;
    float acc = cb[d];
#pragma unroll
    for (int k = 0; k < 4; k++) {
        const int tt = t - 3 + k;
        if (tt >= 0) acc = fmaf(g_xr[(size_t)tt * (2 * DI) + d], cw[k * DI + d], acc);
    }
    g_u[idx] = acc / (1.f + __expf(-acc));
}

// ============================================================
// scan phases
// ============================================================
__global__ void scan_phase1(const float* __restrict__ a_log)
{
    const int c = blockIdx.y;
    const int d = blockIdx.x * 256 + threadIdx.x;
    __shared__ float bs[CLEN][DS];
    for (int i = threadIdx.x; i < CLEN * DS; i += 256) {
        const int t = i / DS, n = i % DS;
        bs[t][n] = g_xdbl[(size_t)(c * CLEN + t) * 80 + RK + n];
    }
    __syncthreads();
    float an[DS];
#pragma unroll
    for (int n = 0; n < DS; n++) an[n] = -__expf(a_log[d * DS + n]);
    float h[DS];
#pragma unroll
    for (int n = 0; n < DS; n++) h[n] = 0.f;
    float s = 0.f;
    for (int t = 0; t < CLEN; t++) {
        const int row = c * CLEN + t;
        const float dl = g_delta[(size_t)row * DI + d];
        const float uv = g_u[(size_t)row * DI + d];
        const float du = dl * uv;
        s += dl;
#pragma unroll
        for (int n = 0; n < DS; n++) {
            const float e = __expf(dl * an[n]);
            h[n] = fmaf(e, h[n], du * bs[t][n]);
        }
    }
    g_send[c * DI + d] = s;
#pragma unroll
    for (int n = 0; n < DS; n++) g_hc[((size_t)c * DI + d) * DS + n] = h[n];
}

__global__ void scan_phase2(const float* __restrict__ a_log)
{
    const int gid = blockIdx.x * 256 + threadIdx.x;
    const int d = gid / DS;
    const float an = -__expf(a_log[gid]);
    float H = 0.f;
    for (int c = 0; c < NCH; c++) {
        const float P = __expf(an * g_send[c * DI + d]);
        const size_t off = ((size_t)c * DI + d) * DS + (gid % DS);
        const float tmp = g_hc[off];
        g_hc[off] = H;
        H = fmaf(P, H, tmp);
    }
}

// phase3: emit y*silu(res) as GEMM4 A operand (hi/lo bf16, row-major)
__global__ void scan_phase3(const float* __restrict__ a_log, const float* __restrict__ dpar)
{
    const int c = blockIdx.y;
    const int d = blockIdx.x * 256 + threadIdx.x;
    __shared__ float bs[CLEN][DS];
    __shared__ float cs[CLEN][DS];
    for (int i = threadIdx.x; i < CLEN * DS; i += 256) {
        const int t = i / DS, n = i % DS;
        bs[t][n] = g_xdbl[(size_t)(c * CLEN + t) * 80 + RK + n];
        cs[t][n] = g_xdbl[(size_t)(c * CLEN + t) * 80 + RK + DS + n];
    }
    __syncthreads();
    float an[DS];
#pragma unroll
    for (int n = 0; n < DS; n++) an[n] = -__expf(a_log[d * DS + n]);
    float h[DS];
#pragma unroll
    for (int n = 0; n < DS; n++) h[n] = g_hc[((size_t)c * DI + d) * DS + n];
    const float Dp = dpar[d];

    for (int t = 0; t < CLEN; t++) {
        const int row = c * CLEN + t;
        const float dl = g_delta[(size_t)row * DI + d];
        const float uv = g_u[(size_t)row * DI + d];
        const float du = dl * uv;
        float y = 0.f;
#pragma unroll
        for (int n = 0; n < DS; n++) {
            const float e = __expf(dl * an[n]);
            h[n] = fmaf(e, h[n], du * bs[t][n]);
            y = fmaf(h[n], cs[t][n], y);
        }
        y = fmaf(uv, Dp, y);
        const float r = g_xr[(size_t)row * (2 * DI) + DI + d];
        const float sr = r / (1.f + __expf(-r));
        const float v = y * sr;
        const __nv_bfloat16 hi = __float2bfloat16(v);
        const size_t o = (size_t)row * DI + d;
        g_a4hi[o] = hi;
        g_a4lo[o] = __float2bfloat16(v - __bfloat162float(hi));
    }
}

// ============================================================
// launch
// ============================================================
extern "C" void kernel_launch(void* const* d_in, const int* in_sizes, int n_in,
                              void* d_out, int out_size)
{
    const float* x         = (const float*)d_in[0];
    const float* in_proj_w = (const float*)d_in[1];
    const float* conv_w    = (const float*)d_in[2];
    const float* conv_b    = (const float*)d_in[3];
    const float* x_proj_w  = (const float*)d_in[4];
    const float* dt_proj_w = (const float*)d_in[5];
    const float* dt_proj_b = (const float*)d_in[6];
    const float* a_log     = (const float*)d_in[7];
    const float* d_param   = (const float*)d_in[8];
    const float* out_proj_w= (const float*)d_in[9];
    float* out = (float*)d_out;

    float *xr, *u, *delta, *xdbl, *x2p;
    cudaGetSymbolAddress((void**)&xr,    g_xr);
    cudaGetSymbolAddress((void**)&u,     g_u);
    cudaGetSymbolAddress((void**)&delta, g_delta);
    cudaGetSymbolAddress((void**)&xdbl,  g_xdbl);
    cudaGetSymbolAddress((void**)&x2p,   g_x2p);
    __nv_bfloat16 *a1h, *a1l, *b1h, *b1l, *a4h, *a4l, *b4h, *b4l;
    cudaGetSymbolAddress((void**)&a1h, g_a1hi);
    cudaGetSymbolAddress((void**)&a1l, g_a1lo);
    cudaGetSymbolAddress((void**)&b1h, g_b1hi);
    cudaGetSymbolAddress((void**)&b1l, g_b1lo);
    cudaGetSymbolAddress((void**)&a4h, g_a4hi);
    cudaGetSymbolAddress((void**)&a4l, g_a4lo);
    cudaGetSymbolAddress((void**)&b4h, g_b4hi);
    cudaGetSymbolAddress((void**)&b4l, g_b4lo);

    cudaFuncSetAttribute(hgemm, cudaFuncAttributeMaxDynamicSharedMemorySize, 98304);

    // operand conversions
    convA<<<(LSEQ * DM + 255) / 256, 256>>>(x, a1h, a1l, LSEQ * DM);
    convBT<<<dim3(DM / 32, (2 * DI) / 32), 256>>>(in_proj_w, b1h, b1l, DM, 2 * DI);
    convBT<<<dim3(DI / 32, DM / 32), 256>>>(out_proj_w, b4h, b4l, DI, DM);

    // GEMM1: [2048,768]@[768,3072] -> g_xr
    hgemm<<<dim3((2 * DI) / 128, LSEQ / 128), 256, 98304>>>(
        a1h, a1l, b1h, b1l, xr, LSEQ, 2 * DI, DM);

    // conv + silu -> u
    conv_silu_kernel<<<(LSEQ * DI) / 256, 256>>>(conv_w, conv_b);

    // GEMM2 (split-K x8): u[2048,1536]@x_proj_w[1536,80] -> partials -> xdbl
    sgemm<0><<<dim3(1, LSEQ / 128, KSPL), 256>>>(u, x_proj_w, x2p, LSEQ, 80, DI, DI, 80, 80, nullptr);
    reduce_splitk<<<(LSEQ * 80 + 255) / 256, 256>>>(x2p, xdbl, LSEQ * 80);

    // GEMM3: xdbl[:,:48]@dt_proj_w[48,1536] + softplus -> delta
    sgemm<1><<<dim3(DI / 128, LSEQ / 128), 256>>>(xdbl, dt_proj_w, delta, LSEQ, DI, RK, 80, DI, DI, dt_proj_b);

    // selective scan
    scan_phase1<<<dim3(DI / 256, NCH), 256>>>(a_log);
    scan_phase2<<<(DI * DS) / 256, 256>>>(a_log);
    scan_phase3<<<dim3(DI / 256, NCH), 256>>>(a_log, d_param);

    // GEMM4: y[2048,1536]@out_proj_w[1536,768] -> out
    hgemm<<<dim3(DM / 128, LSEQ / 128), 256, 98304>>>(
        a4h, a4l, b4h, b4l, out, LSEQ, DM, DI);
}

// round 6
// speedup vs baseline: 2.7701x; 1.0386x over previous
#include <cuda_runtime.h>
#include <cuda_bf16.h>
#include <math.h>
#include <stdint.h>

#define LSEQ 2048
#define DM   768
#define DI   1536
#define RK   48
#define DS   16
#define NCH  64
#define CLEN 32
#define KSPL 8      // K-split factor for GEMM2

// ---------------- static scratch ----------------
__device__ float g_xr[LSEQ * 2 * DI];
__device__ float g_u[LSEQ * DI];
__device__ float g_delta[LSEQ * DI];
__device__ float g_xdbl[LSEQ * 80];
__device__ float g_x2p[KSPL * LSEQ * 80];   // GEMM2 split-K partials
__device__ float g_o4p[2 * LSEQ * DM];      // GEMM4 split-K partials
__device__ float g_hc[NCH * DI * DS];
__device__ float g_send[NCH * DI];

// bf16 hi/lo operands (plain row-major; B pre-transposed to [N,K])
__device__ __align__(16) __nv_bfloat16 g_a1hi[LSEQ * DM];
__device__ __align__(16) __nv_bfloat16 g_a1lo[LSEQ * DM];
__device__ __align__(16) __nv_bfloat16 g_b1hi[(2*DI) * DM];
__device__ __align__(16) __nv_bfloat16 g_b1lo[(2*DI) * DM];
__device__ __align__(16) __nv_bfloat16 g_a4hi[LSEQ * DI];
__device__ __align__(16) __nv_bfloat16 g_a4lo[LSEQ * DI];
__device__ __align__(16) __nv_bfloat16 g_b4hi[DM * DI];
__device__ __align__(16) __nv_bfloat16 g_b4lo[DM * DI];

// ---------------- helpers ----------------
__device__ __forceinline__ uint32_t smem_u32(const void* p) {
    uint32_t a;
    asm("{ .reg .u64 t; cvta.to.shared.u64 t, %1; cvt.u32.u64 %0, t; }" : "=r"(a) : "l"(p));
    return a;
}

__device__ __forceinline__ void cp16(uint32_t dst, const void* src) {
    asm volatile("cp.async.cg.shared.global [%0], [%1], 16;" :: "r"(dst), "l"(src) : "memory");
}
__device__ __forceinline__ void cp_commit() { asm volatile("cp.async.commit_group;" ::: "memory"); }
__device__ __forceinline__ void cp_wait1()  { asm volatile("cp.async.wait_group 1;" ::: "memory"); }

__device__ __forceinline__ void ldsm4(uint32_t* r, uint32_t addr) {
    asm volatile("ldmatrix.sync.aligned.m8n8.x4.shared.b16 {%0,%1,%2,%3}, [%4];"
                 : "=r"(r[0]), "=r"(r[1]), "=r"(r[2]), "=r"(r[3]) : "r"(addr));
}

__device__ __forceinline__ void mma16816(float* c, const uint32_t* a, const uint32_t* b) {
    asm volatile("mma.sync.aligned.m16n8k16.row.col.f32.bf16.bf16.f32 "
                 "{%0,%1,%2,%3}, {%4,%5,%6,%7}, {%8,%9}, {%0,%1,%2,%3};"
                 : "+f"(c[0]), "+f"(c[1]), "+f"(c[2]), "+f"(c[3])
                 : "r"(a[0]), "r"(a[1]), "r"(a[2]), "r"(a[3]), "r"(b[0]), "r"(b[1]));
}

// conflict-free swizzle for [row][32 bf16] tiles (64B rows, 16B chunks)
__device__ __forceinline__ uint32_t soff(int r, int c) {
    return (uint32_t)(r * 64 + ((c ^ ((r >> 1) & 3)) << 4));
}

// ============================================================
// bf16 tensor-core GEMM: C[M,N] = A@B^T(stored [N,K]), 3x split.
// Tile 128x128x32, 256 threads, 2-stage cp.async pipeline, 2 CTA/SM.
// Optional split-K via gridDim.z (partials at C + z*M*N).
// M%128==0, N%128==0, (K/gridDim.z)%32==0.
// ============================================================
__global__ __launch_bounds__(256, 2)
void hgemm(const __nv_bfloat16* __restrict__ Ahi, const __nv_bfloat16* __restrict__ Alo,
           const __nv_bfloat16* __restrict__ Bhi, const __nv_bfloat16* __restrict__ Blo,
           float* __restrict__ C, int M, int N, int K)
{
    extern __shared__ __align__(128) char smem[];
    const uint32_t sb = smem_u32(smem);
    const int tid = threadIdx.x;
    const int w   = tid >> 5, lid = tid & 31;
    const int wm  = (w >> 2) * 64;      // warp M offset (2 warps)
    const int wn  = (w & 3) * 32;       // warp N offset (4 warps)
    const int bm  = blockIdx.y * 128, bn = blockIdx.x * 128;

    // split-K
    const int Kc   = K / gridDim.z;
    const int kbeg = blockIdx.z * Kc;
    const int KT   = Kc >> 5;
    C += (size_t)blockIdx.z * M * N;

    // per-thread cp.async assignment: row = tid>>1, chunks (tid&1)*2 + {0,1}
    const int prow = tid >> 1;
    const int pc0  = (tid & 1) * 2;

    const __nv_bfloat16* gA[2] = {Ahi, Alo};
    const __nv_bfloat16* gB[2] = {Bhi, Blo};

    auto prefetch = [&](int kt) {
        const int s = kt & 1;
        const uint32_t st = sb + s * 32768;
        const int k0 = kbeg + kt * 32;
#pragma unroll
        for (int hb = 0; hb < 2; hb++) {
            const __nv_bfloat16* srcA = gA[hb] + (size_t)(bm + prow) * K + k0;
            const __nv_bfloat16* srcB = gB[hb] + (size_t)(bn + prow) * K + k0;
            const uint32_t dA = st + hb * 8192;
            const uint32_t dB = st + 16384 + hb * 8192;
#pragma unroll
            for (int cc = 0; cc < 2; cc++) {
                const int c = pc0 + cc;
                cp16(dA + soff(prow, c), srcA + c * 8);
                cp16(dB + soff(prow, c), srcB + c * 8);
            }
        }
    };

    float acc[4][4][4];
#pragma unroll
    for (int i = 0; i < 4; i++)
#pragma unroll
        for (int j = 0; j < 4; j++)
#pragma unroll
            for (int e = 0; e < 4; e++) acc[i][j][e] = 0.f;

    prefetch(0); cp_commit();
    if (KT > 1) { prefetch(1); } cp_commit();

    // ldmatrix lane geometry (constant per thread)
    const int lrA = ((lid >> 3) & 1) * 8 + (lid & 7);
    const int lhA = (lid >> 4) & 1;          // k-half for A
    const int jB  = lid >> 3;
    const int lrB = ((jB >> 1) & 1) * 8 + (lid & 7);
    const int lhB = jB & 1;                  // k-half for B

    for (int kt = 0; kt < KT; kt++) {
        cp_wait1();
        __syncthreads();
        const uint32_t st = sb + (kt & 1) * 32768;
#pragma unroll
        for (int ks = 0; ks < 2; ks++) {
            uint32_t ah[4][4], al[4][4], bh[2][4], bl[2][4];
            const int cA = ks * 2 + lhA;
            const int cB = ks * 2 + lhB;
#pragma unroll
            for (int mi = 0; mi < 4; mi++) {
                const uint32_t ad = st + soff(wm + mi * 16 + lrA, cA);
                ldsm4(ah[mi], ad);
                ldsm4(al[mi], ad + 8192);
            }
#pragma unroll
            for (int nf2 = 0; nf2 < 2; nf2++) {
                const uint32_t bd = st + 16384 + soff(wn + nf2 * 16 + lrB, cB);
                ldsm4(bh[nf2], bd);
                ldsm4(bl[nf2], bd + 8192);
            }
#pragma unroll
            for (int mi = 0; mi < 4; mi++) {
#pragma unroll
                for (int nf = 0; nf < 4; nf++) {
                    float* c = acc[mi][nf];
                    const uint32_t* B1 = &bh[nf >> 1][(nf & 1) * 2];
                    const uint32_t* B2 = &bl[nf >> 1][(nf & 1) * 2];
                    mma16816(c, ah[mi], B1);
                    mma16816(c, ah[mi], B2);
                    mma16816(c, al[mi], B1);
                }
            }
        }
        __syncthreads();
        if (kt + 2 < KT) prefetch(kt + 2);
        cp_commit();
    }

    // epilogue: lane holds (g,2t) pairs
    const int g = lid >> 2, t2 = (lid & 3) * 2;
#pragma unroll
    for (int mi = 0; mi < 4; mi++) {
        const int row0 = bm + wm + mi * 16 + g;
#pragma unroll
        for (int nf = 0; nf < 4; nf++) {
            const int col = bn + wn + nf * 8 + t2;
            float2 v0 = {acc[mi][nf][0], acc[mi][nf][1]};
            float2 v1 = {acc[mi][nf][2], acc[mi][nf][3]};
            *reinterpret_cast<float2*>(&C[(size_t)row0 * N + col]) = v0;
            *reinterpret_cast<float2*>(&C[(size_t)(row0 + 8) * N + col]) = v1;
        }
    }
}

// ============================================================
// conversions
// ============================================================
__global__ void convA(const float* __restrict__ src, __nv_bfloat16* __restrict__ hi,
                      __nv_bfloat16* __restrict__ lo, int total)
{
    const int idx = blockIdx.x * 256 + threadIdx.x;
    if (idx >= total) return;
    const float v = src[idx];
    const __nv_bfloat16 h = __float2bfloat16(v);
    hi[idx] = h;
    lo[idx] = __float2bfloat16(v - __bfloat162float(h));
}

// transpose+convert: src[K,N] fp32 -> hi/lo [N,K] bf16
__global__ void convBT(const float* __restrict__ src, __nv_bfloat16* __restrict__ hi,
                       __nv_bfloat16* __restrict__ lo, int K, int N)
{
    __shared__ float s[32][33];
    const int k0 = blockIdx.x * 32, n0 = blockIdx.y * 32;
    const int tx = threadIdx.x & 31, ty = threadIdx.x >> 5;
#pragma unroll
    for (int i = 0; i < 4; i++) {
        const int kr = i * 8 + ty;
        s[kr][tx] = src[(size_t)(k0 + kr) * N + n0 + tx];
    }
    __syncthreads();
#pragma unroll
    for (int i = 0; i < 4; i++) {
        const int nl = i * 8 + ty;
        const int n = n0 + nl, k = k0 + tx;
        const float v = s[tx][nl];
        const __nv_bfloat16 h = __float2bfloat16(v);
        const size_t o = (size_t)n * K + k;
        hi[o] = h;
        lo[o] = __float2bfloat16(v - __bfloat162float(h));
    }
}

// ============================================================
// SIMT fp32 GEMM (small GEMMs 2 & 3), optional split-K via gridDim.z
// ============================================================
template <int EPI>
__launch_bounds__(256)
__global__ void sgemm(const float* __restrict__ A, const float* __restrict__ B,
                      float* __restrict__ C, int M, int N, int K,
                      int lda, int ldb, int ldc, const float* __restrict__ bias)
{
    __shared__ __align__(16) float As[8][128];
    __shared__ __align__(16) float Bs[8][128];
    const int tid = threadIdx.x;
    const int bm = blockIdx.y * 128, bn = blockIdx.x * 128;
    const int arow = tid >> 1, acol = (tid & 1) * 4;
    const int brow = tid >> 5, bcol = (tid & 31) * 4;
    const int tr = (tid >> 4) * 8, tc = (tid & 15) * 8;

    const int Kc = K / gridDim.z;
    const int kbeg = blockIdx.z * Kc;
    const int kend = kbeg + Kc;
    C += (size_t)blockIdx.z * M * ldc;

    float acc[8][8];
#pragma unroll
    for (int i = 0; i < 8; i++)
#pragma unroll
        for (int j = 0; j < 8; j++) acc[i][j] = 0.f;

    for (int k0 = kbeg; k0 < kend; k0 += 8) {
        {
            const float4 a = *reinterpret_cast<const float4*>(&A[(size_t)(bm + arow) * lda + k0 + acol]);
            As[acol + 0][arow] = a.x; As[acol + 1][arow] = a.y;
            As[acol + 2][arow] = a.z; As[acol + 3][arow] = a.w;
        }
        {
            const int col = bn + bcol;
            if (col + 3 < N) {
                *reinterpret_cast<float4*>(&Bs[brow][bcol]) =
                    *reinterpret_cast<const float4*>(&B[(size_t)(k0 + brow) * ldb + col]);
            } else {
#pragma unroll
                for (int j = 0; j < 4; j++)
                    Bs[brow][bcol + j] = (col + j < N) ? B[(size_t)(k0 + brow) * ldb + col + j] : 0.f;
            }
        }
        __syncthreads();
#pragma unroll
        for (int kk = 0; kk < 8; kk++) {
            float4 a0 = *reinterpret_cast<const float4*>(&As[kk][tr]);
            float4 a1 = *reinterpret_cast<const float4*>(&As[kk][tr + 4]);
            float4 b0 = *reinterpret_cast<const float4*>(&Bs[kk][tc]);
            float4 b1 = *reinterpret_cast<const float4*>(&Bs[kk][tc + 4]);
            float af[8] = {a0.x, a0.y, a0.z, a0.w, a1.x, a1.y, a1.z, a1.w};
            float bf[8] = {b0.x, b0.y, b0.z, b0.w, b1.x, b1.y, b1.z, b1.w};
#pragma unroll
            for (int i = 0; i < 8; i++)
#pragma unroll
                for (int j = 0; j < 8; j++) acc[i][j] = fmaf(af[i], bf[j], acc[i][j]);
        }
        __syncthreads();
    }
#pragma unroll
    for (int i = 0; i < 8; i++) {
        const int row = bm + tr + i;
#pragma unroll
        for (int j = 0; j < 8; j++) {
            const int col = bn + tc + j;
            if (col < N) {
                float v = acc[i][j];
                if (EPI == 1) {
                    v = v + bias[col];
                    v = fmaxf(v, 0.f) + log1pf(__expf(-fabsf(v)));
                }
                C[(size_t)row * ldc + col] = v;
            }
        }
    }
}

// reduce KSPL split-K partial layers -> final
__global__ void reduce_splitk(const float* __restrict__ p, float* __restrict__ o, int n)
{
    const int i = blockIdx.x * 256 + threadIdx.x;
    if (i >= n) return;
    float s = 0.f;
#pragma unroll
    for (int z = 0; z < KSPL; z++) s += p[(size_t)z * n + i];
    o[i] = s;
}

// reduce 2 layers (vectorized)
__global__ void reduce2(const float* __restrict__ p, float* __restrict__ o, int n4)
{
    const int i = blockIdx.x * 256 + threadIdx.x;
    if (i >= n4) return;
    const float4 a = reinterpret_cast<const float4*>(p)[i];
    const float4 b = reinterpret_cast<const float4*>(p)[i + n4];
    float4 r = {a.x + b.x, a.y + b.y, a.z + b.z, a.w + b.w};
    reinterpret_cast<float4*>(o)[i] = r;
}

// ============================================================
// conv + silu
// ============================================================
__global__ void conv_silu_kernel(const float* __restrict__ cw, const float* __restrict__ cb)
{
    const int idx = blockIdx.x * blockDim.x + threadIdx.x;
    const int d = idx % DI, t = idx / DI;
    float acc = cb[d];
#pragma unroll
    for (int k = 0; k < 4; k++) {
        const int tt = t - 3 + k;
        if (tt >= 0) acc = fmaf(g_xr[(size_t)tt * (2 * DI) + d], cw[k * DI + d], acc);
    }
    g_u[idx] = acc / (1.f + __expf(-acc));
}

// ============================================================
// scan phases
// ============================================================
__global__ void scan_phase1(const float* __restrict__ a_log)
{
    const int c = blockIdx.y;
    const int d = blockIdx.x * 256 + threadIdx.x;
    __shared__ float bs[CLEN][DS];
    for (int i = threadIdx.x; i < CLEN * DS; i += 256) {
        const int t = i / DS, n = i % DS;
        bs[t][n] = g_xdbl[(size_t)(c * CLEN + t) * 80 + RK + n];
    }
    __syncthreads();
    float an[DS];
#pragma unroll
    for (int n = 0; n < DS; n++) an[n] = -__expf(a_log[d * DS + n]);
    float h[DS];
#pragma unroll
    for (int n = 0; n < DS; n++) h[n] = 0.f;
    float s = 0.f;
    for (int t = 0; t < CLEN; t++) {
        const int row = c * CLEN + t;
        const float dl = g_delta[(size_t)row * DI + d];
        const float uv = g_u[(size_t)row * DI + d];
        const float du = dl * uv;
        s += dl;
#pragma unroll
        for (int n = 0; n < DS; n++) {
            const float e = __expf(dl * an[n]);
            h[n] = fmaf(e, h[n], du * bs[t][n]);
        }
    }
    g_send[c * DI + d] = s;
#pragma unroll
    for (int n = 0; n < DS; n++) g_hc[((size_t)c * DI + d) * DS + n] = h[n];
}

__global__ void scan_phase2(const float* __restrict__ a_log)
{
    const int gid = blockIdx.x * 256 + threadIdx.x;
    const int d = gid / DS;
    const float an = -__expf(a_log[gid]);
    float H = 0.f;
    for (int c = 0; c < NCH; c++) {
        const float P = __expf(an * g_send[c * DI + d]);
        const size_t off = ((size_t)c * DI + d) * DS + (gid % DS);
        const float tmp = g_hc[off];
        g_hc[off] = H;
        H = fmaf(P, H, tmp);
    }
}

// phase3: emit y*silu(res) as GEMM4 A operand (hi/lo bf16, row-major)
__global__ void scan_phase3(const float* __restrict__ a_log, const float* __restrict__ dpar)
{
    const int c = blockIdx.y;
    const int d = blockIdx.x * 256 + threadIdx.x;
    __shared__ float bs[CLEN][DS];
    __shared__ float cs[CLEN][DS];
    for (int i = threadIdx.x; i < CLEN * DS; i += 256) {
        const int t = i / DS, n = i % DS;
        bs[t][n] = g_xdbl[(size_t)(c * CLEN + t) * 80 + RK + n];
        cs[t][n] = g_xdbl[(size_t)(c * CLEN + t) * 80 + RK + DS + n];
    }
    __syncthreads();
    float an[DS];
#pragma unroll
    for (int n = 0; n < DS; n++) an[n] = -__expf(a_log[d * DS + n]);
    float h[DS];
#pragma unroll
    for (int n = 0; n < DS; n++) h[n] = g_hc[((size_t)c * DI + d) * DS + n];
    const float Dp = dpar[d];

    for (int t = 0; t < CLEN; t++) {
        const int row = c * CLEN + t;
        const float dl = g_delta[(size_t)row * DI + d];
        const float uv = g_u[(size_t)row * DI + d];
        const float du = dl * uv;
        float y = 0.f;
#pragma unroll
        for (int n = 0; n < DS; n++) {
            const float e = __expf(dl * an[n]);
            h[n] = fmaf(e, h[n], du * bs[t][n]);
            y = fmaf(h[n], cs[t][n], y);
        }
        y = fmaf(uv, Dp, y);
        const float r = g_xr[(size_t)row * (2 * DI) + DI + d];
        const float sr = r / (1.f + __expf(-r));
        const float v = y * sr;
        const __nv_bfloat16 hi = __float2bfloat16(v);
        const size_t o = (size_t)row * DI + d;
        g_a4hi[o] = hi;
        g_a4lo[o] = __float2bfloat16(v - __bfloat162float(hi));
    }
}

// ============================================================
// launch
// ============================================================
extern "C" void kernel_launch(void* const* d_in, const int* in_sizes, int n_in,
                              void* d_out, int out_size)
{
    const float* x         = (const float*)d_in[0];
    const float* in_proj_w = (const float*)d_in[1];
    const float* conv_w    = (const float*)d_in[2];
    const float* conv_b    = (const float*)d_in[3];
    const float* x_proj_w  = (const float*)d_in[4];
    const float* dt_proj_w = (const float*)d_in[5];
    const float* dt_proj_b = (const float*)d_in[6];
    const float* a_log     = (const float*)d_in[7];
    const float* d_param   = (const float*)d_in[8];
    const float* out_proj_w= (const float*)d_in[9];
    float* out = (float*)d_out;

    float *xr, *u, *delta, *xdbl, *x2p, *o4p;
    cudaGetSymbolAddress((void**)&xr,    g_xr);
    cudaGetSymbolAddress((void**)&u,     g_u);
    cudaGetSymbolAddress((void**)&delta, g_delta);
    cudaGetSymbolAddress((void**)&xdbl,  g_xdbl);
    cudaGetSymbolAddress((void**)&x2p,   g_x2p);
    cudaGetSymbolAddress((void**)&o4p,   g_o4p);
    __nv_bfloat16 *a1h, *a1l, *b1h, *b1l, *a4h, *a4l, *b4h, *b4l;
    cudaGetSymbolAddress((void**)&a1h, g_a1hi);
    cudaGetSymbolAddress((void**)&a1l, g_a1lo);
    cudaGetSymbolAddress((void**)&b1h, g_b1hi);
    cudaGetSymbolAddress((void**)&b1l, g_b1lo);
    cudaGetSymbolAddress((void**)&a4h, g_a4hi);
    cudaGetSymbolAddress((void**)&a4l, g_a4lo);
    cudaGetSymbolAddress((void**)&b4h, g_b4hi);
    cudaGetSymbolAddress((void**)&b4l, g_b4lo);

    cudaFuncSetAttribute(hgemm, cudaFuncAttributeMaxDynamicSharedMemorySize, 65536);

    // operand conversions
    convA<<<(LSEQ * DM + 255) / 256, 256>>>(x, a1h, a1l, LSEQ * DM);
    convBT<<<dim3(DM / 32, (2 * DI) / 32), 256>>>(in_proj_w, b1h, b1l, DM, 2 * DI);
    convBT<<<dim3(DI / 32, DM / 32), 256>>>(out_proj_w, b4h, b4l, DI, DM);

    // GEMM1: [2048,768]@[768,3072] -> g_xr
    hgemm<<<dim3((2 * DI) / 128, LSEQ / 128, 1), 256, 65536>>>(
        a1h, a1l, b1h, b1l, xr, LSEQ, 2 * DI, DM);

    // conv + silu -> u
    conv_silu_kernel<<<(LSEQ * DI) / 256, 256>>>(conv_w, conv_b);

    // GEMM2 (split-K x8): u[2048,1536]@x_proj_w[1536,80] -> partials -> xdbl
    sgemm<0><<<dim3(1, LSEQ / 128, KSPL), 256>>>(u, x_proj_w, x2p, LSEQ, 80, DI, DI, 80, 80, nullptr);
    reduce_splitk<<<(LSEQ * 80 + 255) / 256, 256>>>(x2p, xdbl, LSEQ * 80);

    // GEMM3: xdbl[:,:48]@dt_proj_w[48,1536] + softplus -> delta
    sgemm<1><<<dim3(DI / 128, LSEQ / 128, 1), 256>>>(xdbl, dt_proj_w, delta, LSEQ, DI, RK, 80, DI, DI, dt_proj_b);

    // selective scan
    scan_phase1<<<dim3(DI / 256, NCH), 256>>>(a_log);
    scan_phase2<<<(DI * DS) / 256, 256>>>(a_log);
    scan_phase3<<<dim3(DI / 256, NCH), 256>>>(a_log, d_param);

    // GEMM4 (split-K x2): y[2048,1536]@out_proj_w[1536,768] -> partials -> out
    hgemm<<<dim3(DM / 128, LSEQ / 128, 2), 256, 65536>>>(
        a4h, a4l, b4h, b4l, o4p, LSEQ, DM, DI);
    reduce2<<<(LSEQ * DM / 4 + 255) / 256, 256>>>(o4p, out, LSEQ * DM / 4);
}

// round 7
// speedup vs baseline: 3.1242x; 1.1278x over previous
#include <cuda_runtime.h>
#include <cuda_bf16.h>
#include <math.h>
#include <stdint.h>

#define LSEQ 2048
#define DM   768
#define DI   1536
#define RK   48
#define DS   16
#define NCH  64
#define CLEN 32
#define KSPL 8      // K-split factor for GEMM2
#define Z4   3      // K-split factor for GEMM4

// ---------------- static scratch ----------------
__device__ float g_xr[LSEQ * 2 * DI];
__device__ float g_u[LSEQ * DI];
__device__ float g_delta[LSEQ * DI];
__device__ float g_xdbl[LSEQ * 80];
__device__ float g_x2p[KSPL * LSEQ * 80];   // GEMM2 split-K partials
__device__ float g_o4p[Z4 * LSEQ * DM];     // GEMM4 split-K partials
__device__ float g_hc[NCH * DI * DS];
__device__ float g_send[NCH * DI];

// bf16 hi/lo operands (row-major; B pre-transposed to [N,K])
__device__ __align__(16) __nv_bfloat16 g_a1hi[LSEQ * DM];
__device__ __align__(16) __nv_bfloat16 g_a1lo[LSEQ * DM];
__device__ __align__(16) __nv_bfloat16 g_b1hi[(2*DI) * DM];
__device__ __align__(16) __nv_bfloat16 g_b1lo[(2*DI) * DM];
__device__ __align__(16) __nv_bfloat16 g_a3hi[LSEQ * RK];
__device__ __align__(16) __nv_bfloat16 g_a3lo[LSEQ * RK];
__device__ __align__(16) __nv_bfloat16 g_b3hi[DI * RK];
__device__ __align__(16) __nv_bfloat16 g_b3lo[DI * RK];
__device__ __align__(16) __nv_bfloat16 g_a4hi[LSEQ * DI];
__device__ __align__(16) __nv_bfloat16 g_a4lo[LSEQ * DI];
__device__ __align__(16) __nv_bfloat16 g_b4hi[DM * DI];
__device__ __align__(16) __nv_bfloat16 g_b4lo[DM * DI];

// ---------------- helpers ----------------
__device__ __forceinline__ uint32_t smem_u32(const void* p) {
    uint32_t a;
    asm("{ .reg .u64 t; cvta.to.shared.u64 t, %1; cvt.u32.u64 %0, t; }" : "=r"(a) : "l"(p));
    return a;
}

__device__ __forceinline__ void cp16(uint32_t dst, const void* src) {
    asm volatile("cp.async.cg.shared.global [%0], [%1], 16;" :: "r"(dst), "l"(src) : "memory");
}
__device__ __forceinline__ void cp_commit() { asm volatile("cp.async.commit_group;" ::: "memory"); }
__device__ __forceinline__ void cp_wait2()  { asm volatile("cp.async.wait_group 2;" ::: "memory"); }

__device__ __forceinline__ void ldsm4(uint32_t* r, uint32_t addr) {
    asm volatile("ldmatrix.sync.aligned.m8n8.x4.shared.b16 {%0,%1,%2,%3}, [%4];"
                 : "=r"(r[0]), "=r"(r[1]), "=r"(r[2]), "=r"(r[3]) : "r"(addr));
}

__device__ __forceinline__ void mma16816(float* c, const uint32_t* a, const uint32_t* b) {
    asm volatile("mma.sync.aligned.m16n8k16.row.col.f32.bf16.bf16.f32 "
                 "{%0,%1,%2,%3}, {%4,%5,%6,%7}, {%8,%9}, {%0,%1,%2,%3};"
                 : "+f"(c[0]), "+f"(c[1]), "+f"(c[2]), "+f"(c[3])
                 : "r"(a[0]), "r"(a[1]), "r"(a[2]), "r"(a[3]), "r"(b[0]), "r"(b[1]));
}

// conflict-free swizzle for [row][16 bf16] tiles (32B rows, 16B chunks)
__device__ __forceinline__ uint32_t soff16(int r, int c) {
    return (uint32_t)(r * 32 + ((c ^ ((r >> 2) & 1)) << 4));
}

// ============================================================
// bf16 tensor-core GEMM: C[M,N] = A@B^T(stored [N,K]), 3x split.
// Tile 128x128x16, 256 threads, 4-stage cp.async pipeline, 2 CTA/SM,
// single __syncthreads per K-iteration. Optional split-K via gridDim.z.
// EPI: 0 = plain, 1 = softplus(acc + bias[col]).
// M%128==0, N%128==0, (K/gridDim.z)%16==0.
// ============================================================
template <int EPI>
__global__ __launch_bounds__(256, 2)
void hgemm(const __nv_bfloat16* __restrict__ Ahi, const __nv_bfloat16* __restrict__ Alo,
           const __nv_bfloat16* __restrict__ Bhi, const __nv_bfloat16* __restrict__ Blo,
           float* __restrict__ C, int M, int N, int K, const float* __restrict__ bias)
{
    extern __shared__ __align__(128) char smem[];
    const uint32_t sb = smem_u32(smem);
    const int tid = threadIdx.x;
    const int w   = tid >> 5, lid = tid & 31;
    const int wm  = (w >> 2) * 64;      // warp M offset (2 warps)
    const int wn  = (w & 3) * 32;       // warp N offset (4 warps)
    const int bm  = blockIdx.y * 128, bn = blockIdx.x * 128;

    // split-K
    const int Kc   = K / gridDim.z;
    const int kbeg = blockIdx.z * Kc;
    const int KT   = Kc >> 4;
    C += (size_t)blockIdx.z * M * N;

    // per-thread cp.async assignment: one 16B chunk per tensor per stage
    const int prow = tid >> 1;
    const int pch  = tid & 1;

    const __nv_bfloat16* gA[2] = {Ahi, Alo};
    const __nv_bfloat16* gB[2] = {Bhi, Blo};

    auto prefetch = [&](int kt) {
        const uint32_t st = sb + (kt & 3) * 16384;
        const int k0 = kbeg + kt * 16 + pch * 8;
#pragma unroll
        for (int hb = 0; hb < 2; hb++) {
            cp16(st + hb * 4096 + soff16(prow, pch),
                 gA[hb] + (size_t)(bm + prow) * K + k0);
            cp16(st + 8192 + hb * 4096 + soff16(prow, pch),
                 gB[hb] + (size_t)(bn + prow) * K + k0);
        }
    };

    float acc[4][4][4];
#pragma unroll
    for (int i = 0; i < 4; i++)
#pragma unroll
        for (int j = 0; j < 4; j++)
#pragma unroll
            for (int e = 0; e < 4; e++) acc[i][j][e] = 0.f;

#pragma unroll
    for (int s = 0; s < 3; s++) {
        if (s < KT) prefetch(s);
        cp_commit();
    }

    // ldmatrix lane geometry
    const int lrA = ((lid >> 3) & 1) * 8 + (lid & 7);
    const int lhA = (lid >> 4) & 1;          // k-chunk for A
    const int jB  = lid >> 3;
    const int lrB = ((jB >> 1) & 1) * 8 + (lid & 7);
    const int lhB = jB & 1;                  // k-chunk for B

    for (int kt = 0; kt < KT; kt++) {
        cp_wait2();
        __syncthreads();
        if (kt + 3 < KT) prefetch(kt + 3);
        cp_commit();

        const uint32_t st = sb + (kt & 3) * 16384;
        uint32_t ah[4][4], al[4][4], bh[2][4], bl[2][4];
#pragma unroll
        for (int mi = 0; mi < 4; mi++) {
            const uint32_t ad = st + soff16(wm + mi * 16 + lrA, lhA);
            ldsm4(ah[mi], ad);
            ldsm4(al[mi], ad + 4096);
        }
#pragma unroll
        for (int nf2 = 0; nf2 < 2; nf2++) {
            const uint32_t bd = st + 8192 + soff16(wn + nf2 * 16 + lrB, lhB);
            ldsm4(bh[nf2], bd);
            ldsm4(bl[nf2], bd + 4096);
        }
#pragma unroll
        for (int mi = 0; mi < 4; mi++) {
#pragma unroll
            for (int nf = 0; nf < 4; nf++) {
                float* c = acc[mi][nf];
                const uint32_t* B1 = &bh[nf >> 1][(nf & 1) * 2];
                const uint32_t* B2 = &bl[nf >> 1][(nf & 1) * 2];
                mma16816(c, ah[mi], B1);
                mma16816(c, ah[mi], B2);
                mma16816(c, al[mi], B1);
            }
        }
    }

    // epilogue: lane holds (g, 2t) pairs
    const int g = lid >> 2, t2 = (lid & 3) * 2;
#pragma unroll
    for (int mi = 0; mi < 4; mi++) {
        const int row0 = bm + wm + mi * 16 + g;
#pragma unroll
        for (int nf = 0; nf < 4; nf++) {
            const int col = bn + wn + nf * 8 + t2;
            float v[4] = {acc[mi][nf][0], acc[mi][nf][1], acc[mi][nf][2], acc[mi][nf][3]};
            if (EPI == 1) {
                const float b0 = bias[col], b1 = bias[col + 1];
#pragma unroll
                for (int e = 0; e < 4; e++) {
                    float t = v[e] + ((e & 1) ? b1 : b0);
                    v[e] = fmaxf(t, 0.f) + log1pf(__expf(-fabsf(t)));
                }
            }
            *reinterpret_cast<float2*>(&C[(size_t)row0 * N + col]) = make_float2(v[0], v[1]);
            *reinterpret_cast<float2*>(&C[(size_t)(row0 + 8) * N + col]) = make_float2(v[2], v[3]);
        }
    }
}

// ============================================================
// conversions
// ============================================================
__global__ void convA(const float* __restrict__ src, __nv_bfloat16* __restrict__ hi,
                      __nv_bfloat16* __restrict__ lo, int total)
{
    const int idx = blockIdx.x * 256 + threadIdx.x;
    if (idx >= total) return;
    const float v = src[idx];
    const __nv_bfloat16 h = __float2bfloat16(v);
    hi[idx] = h;
    lo[idx] = __float2bfloat16(v - __bfloat162float(h));
}

// strided: take first Ksub cols of src[M, lda] -> packed [M, Ksub] hi/lo
__global__ void convA_strided(const float* __restrict__ src, __nv_bfloat16* __restrict__ hi,
                              __nv_bfloat16* __restrict__ lo, int M, int Ksub, int lda)
{
    const int idx = blockIdx.x * 256 + threadIdx.x;
    if (idx >= M * Ksub) return;
    const int m = idx / Ksub, k = idx % Ksub;
    const float v = src[(size_t)m * lda + k];
    const __nv_bfloat16 h = __float2bfloat16(v);
    hi[idx] = h;
    lo[idx] = __float2bfloat16(v - __bfloat162float(h));
}

// transpose+convert: src[K,N] fp32 -> hi/lo [N,K] bf16 (K may be non-mult of 32)
__global__ void convBT(const float* __restrict__ src, __nv_bfloat16* __restrict__ hi,
                       __nv_bfloat16* __restrict__ lo, int K, int N)
{
    __shared__ float s[32][33];
    const int k0 = blockIdx.x * 32, n0 = blockIdx.y * 32;
    const int tx = threadIdx.x & 31, ty = threadIdx.x >> 5;
#pragma unroll
    for (int i = 0; i < 4; i++) {
        const int kr = i * 8 + ty;
        s[kr][tx] = (k0 + kr < K) ? src[(size_t)(k0 + kr) * N + n0 + tx] : 0.f;
    }
    __syncthreads();
#pragma unroll
    for (int i = 0; i < 4; i++) {
        const int nl = i * 8 + ty;
        const int n = n0 + nl, k = k0 + tx;
        if (k >= K) continue;
        const float v = s[tx][nl];
        const __nv_bfloat16 h = __float2bfloat16(v);
        const size_t o = (size_t)n * K + k;
        hi[o] = h;
        lo[o] = __float2bfloat16(v - __bfloat162float(h));
    }
}

// ============================================================
// SIMT fp32 GEMM (GEMM2 only), split-K via gridDim.z
// ============================================================
template <int EPI>
__launch_bounds__(256)
__global__ void sgemm(const float* __restrict__ A, const float* __restrict__ B,
                      float* __restrict__ C, int M, int N, int K,
                      int lda, int ldb, int ldc, const float* __restrict__ bias)
{
    __shared__ __align__(16) float As[8][128];
    __shared__ __align__(16) float Bs[8][128];
    const int tid = threadIdx.x;
    const int bm = blockIdx.y * 128, bn = blockIdx.x * 128;
    const int arow = tid >> 1, acol = (tid & 1) * 4;
    const int brow = tid >> 5, bcol = (tid & 31) * 4;
    const int tr = (tid >> 4) * 8, tc = (tid & 15) * 8;

    const int Kc = K / gridDim.z;
    const int kbeg = blockIdx.z * Kc;
    const int kend = kbeg + Kc;
    C += (size_t)blockIdx.z * M * ldc;

    float acc[8][8];
#pragma unroll
    for (int i = 0; i < 8; i++)
#pragma unroll
        for (int j = 0; j < 8; j++) acc[i][j] = 0.f;

    for (int k0 = kbeg; k0 < kend; k0 += 8) {
        {
            const float4 a = *reinterpret_cast<const float4*>(&A[(size_t)(bm + arow) * lda + k0 + acol]);
            As[acol + 0][arow] = a.x; As[acol + 1][arow] = a.y;
            As[acol + 2][arow] = a.z; As[acol + 3][arow] = a.w;
        }
        {
            const int col = bn + bcol;
            if (col + 3 < N) {
                *reinterpret_cast<float4*>(&Bs[brow][bcol]) =
                    *reinterpret_cast<const float4*>(&B[(size_t)(k0 + brow) * ldb + col]);
            } else {
#pragma unroll
                for (int j = 0; j < 4; j++)
                    Bs[brow][bcol + j] = (col + j < N) ? B[(size_t)(k0 + brow) * ldb + col + j] : 0.f;
            }
        }
        __syncthreads();
#pragma unroll
        for (int kk = 0; kk < 8; kk++) {
            float4 a0 = *reinterpret_cast<const float4*>(&As[kk][tr]);
            float4 a1 = *reinterpret_cast<const float4*>(&As[kk][tr + 4]);
            float4 b0 = *reinterpret_cast<const float4*>(&Bs[kk][tc]);
            float4 b1 = *reinterpret_cast<const float4*>(&Bs[kk][tc + 4]);
            float af[8] = {a0.x, a0.y, a0.z, a0.w, a1.x, a1.y, a1.z, a1.w};
            float bf[8] = {b0.x, b0.y, b0.z, b0.w, b1.x, b1.y, b1.z, b1.w};
#pragma unroll
            for (int i = 0; i < 8; i++)
#pragma unroll
                for (int j = 0; j < 8; j++) acc[i][j] = fmaf(af[i], bf[j], acc[i][j]);
        }
        __syncthreads();
    }
#pragma unroll
    for (int i = 0; i < 8; i++) {
        const int row = bm + tr + i;
#pragma unroll
        for (int j = 0; j < 8; j++) {
            const int col = bn + tc + j;
            if (col < N) {
                float v = acc[i][j];
                if (EPI == 1) {
                    v = v + bias[col];
                    v = fmaxf(v, 0.f) + log1pf(__expf(-fabsf(v)));
                }
                C[(size_t)row * ldc + col] = v;
            }
        }
    }
}

// reduce KSPL split-K partial layers -> final
__global__ void reduce_splitk(const float* __restrict__ p, float* __restrict__ o, int n)
{
    const int i = blockIdx.x * 256 + threadIdx.x;
    if (i >= n) return;
    float s = 0.f;
#pragma unroll
    for (int z = 0; z < KSPL; z++) s += p[(size_t)z * n + i];
    o[i] = s;
}

// reduce Z layers (vectorized)
template <int Z>
__global__ void reduceN(const float* __restrict__ p, float* __restrict__ o, int n4)
{
    const int i = blockIdx.x * 256 + threadIdx.x;
    if (i >= n4) return;
    float4 r = reinterpret_cast<const float4*>(p)[i];
#pragma unroll
    for (int z = 1; z < Z; z++) {
        const float4 a = reinterpret_cast<const float4*>(p)[(size_t)z * n4 + i];
        r.x += a.x; r.y += a.y; r.z += a.z; r.w += a.w;
    }
    reinterpret_cast<float4*>(o)[i] = r;
}

// ============================================================
// conv + silu
// ============================================================
__global__ void conv_silu_kernel(const float* __restrict__ cw, const float* __restrict__ cb)
{
    const int idx = blockIdx.x * blockDim.x + threadIdx.x;
    const int d = idx % DI, t = idx / DI;
    float acc = cb[d];
#pragma unroll
    for (int k = 0; k < 4; k++) {
        const int tt = t - 3 + k;
        if (tt >= 0) acc = fmaf(g_xr[(size_t)tt * (2 * DI) + d], cw[k * DI + d], acc);
    }
    g_u[idx] = acc / (1.f + __expf(-acc));
}

// ============================================================
// scan phases
// ============================================================
__global__ void scan_phase1(const float* __restrict__ a_log)
{
    const int c = blockIdx.y;
    const int d = blockIdx.x * 256 + threadIdx.x;
    __shared__ float bs[CLEN][DS];
    for (int i = threadIdx.x; i < CLEN * DS; i += 256) {
        const int t = i / DS, n = i % DS;
        bs[t][n] = g_xdbl[(size_t)(c * CLEN + t) * 80 + RK + n];
    }
    __syncthreads();
    float an[DS];
#pragma unroll
    for (int n = 0; n < DS; n++) an[n] = -__expf(a_log[d * DS + n]);
    float h[DS];
#pragma unroll
    for (int n = 0; n < DS; n++) h[n] = 0.f;
    float s = 0.f;
    for (int t = 0; t < CLEN; t++) {
        const int row = c * CLEN + t;
        const float dl = g_delta[(size_t)row * DI + d];
        const float uv = g_u[(size_t)row * DI + d];
        const float du = dl * uv;
        s += dl;
#pragma unroll
        for (int n = 0; n < DS; n++) {
            const float e = __expf(dl * an[n]);
            h[n] = fmaf(e, h[n], du * bs[t][n]);
        }
    }
    g_send[c * DI + d] = s;
#pragma unroll
    for (int n = 0; n < DS; n++) g_hc[((size_t)c * DI + d) * DS + n] = h[n];
}

__global__ void scan_phase2(const float* __restrict__ a_log)
{
    const int gid = blockIdx.x * 256 + threadIdx.x;
    const int d = gid / DS;
    const float an = -__expf(a_log[gid]);
    float H = 0.f;
    for (int c = 0; c < NCH; c++) {
        const float P = __expf(an * g_send[c * DI + d]);
        const size_t off = ((size_t)c * DI + d) * DS + (gid % DS);
        const float tmp = g_hc[off];
        g_hc[off] = H;
        H = fmaf(P, H, tmp);
    }
}

// phase3: emit y*silu(res) as GEMM4 A operand (hi/lo bf16, row-major)
__global__ void scan_phase3(const float* __restrict__ a_log, const float* __restrict__ dpar)
{
    const int c = blockIdx.y;
    const int d = blockIdx.x * 256 + threadIdx.x;
    __shared__ float bs[CLEN][DS];
    __shared__ float cs[CLEN][DS];
    for (int i = threadIdx.x; i < CLEN * DS; i += 256) {
        const int t = i / DS, n = i % DS;
        bs[t][n] = g_xdbl[(size_t)(c * CLEN + t) * 80 + RK + n];
        cs[t][n] = g_xdbl[(size_t)(c * CLEN + t) * 80 + RK + DS + n];
    }
    __syncthreads();
    float an[DS];
#pragma unroll
    for (int n = 0; n < DS; n++) an[n] = -__expf(a_log[d * DS + n]);
    float h[DS];
#pragma unroll
    for (int n = 0; n < DS; n++) h[n] = g_hc[((size_t)c * DI + d) * DS + n];
    const float Dp = dpar[d];

    for (int t = 0; t < CLEN; t++) {
        const int row = c * CLEN + t;
        const float dl = g_delta[(size_t)row * DI + d];
        const float uv = g_u[(size_t)row * DI + d];
        const float du = dl * uv;
        float y = 0.f;
#pragma unroll
        for (int n = 0; n < DS; n++) {
            const float e = __expf(dl * an[n]);
            h[n] = fmaf(e, h[n], du * bs[t][n]);
            y = fmaf(h[n], cs[t][n], y);
        }
        y = fmaf(uv, Dp, y);
        const float r = g_xr[(size_t)row * (2 * DI) + DI + d];
        const float sr = r / (1.f + __expf(-r));
        const float v = y * sr;
        const __nv_bfloat16 hi = __float2bfloat16(v);
        const size_t o = (size_t)row * DI + d;
        g_a4hi[o] = hi;
        g_a4lo[o] = __float2bfloat16(v - __bfloat162float(hi));
    }
}

// ============================================================
// launch
// ============================================================
extern "C" void kernel_launch(void* const* d_in, const int* in_sizes, int n_in,
                              void* d_out, int out_size)
{
    const float* x         = (const float*)d_in[0];
    const float* in_proj_w = (const float*)d_in[1];
    const float* conv_w    = (const float*)d_in[2];
    const float* conv_b    = (const float*)d_in[3];
    const float* x_proj_w  = (const float*)d_in[4];
    const float* dt_proj_w = (const float*)d_in[5];
    const float* dt_proj_b = (const float*)d_in[6];
    const float* a_log     = (const float*)d_in[7];
    const float* d_param   = (const float*)d_in[8];
    const float* out_proj_w= (const float*)d_in[9];
    float* out = (float*)d_out;

    float *xr, *u, *delta, *xdbl, *x2p, *o4p;
    cudaGetSymbolAddress((void**)&xr,    g_xr);
    cudaGetSymbolAddress((void**)&u,     g_u);
    cudaGetSymbolAddress((void**)&delta, g_delta);
    cudaGetSymbolAddress((void**)&xdbl,  g_xdbl);
    cudaGetSymbolAddress((void**)&x2p,   g_x2p);
    cudaGetSymbolAddress((void**)&o4p,   g_o4p);
    __nv_bfloat16 *a1h, *a1l, *b1h, *b1l, *a3h, *a3l, *b3h, *b3l, *a4h, *a4l, *b4h, *b4l;
    cudaGetSymbolAddress((void**)&a1h, g_a1hi);
    cudaGetSymbolAddress((void**)&a1l, g_a1lo);
    cudaGetSymbolAddress((void**)&b1h, g_b1hi);
    cudaGetSymbolAddress((void**)&b1l, g_b1lo);
    cudaGetSymbolAddress((void**)&a3h, g_a3hi);
    cudaGetSymbolAddress((void**)&a3l, g_a3lo);
    cudaGetSymbolAddress((void**)&b3h, g_b3hi);
    cudaGetSymbolAddress((void**)&b3l, g_b3lo);
    cudaGetSymbolAddress((void**)&a4h, g_a4hi);
    cudaGetSymbolAddress((void**)&a4l, g_a4lo);
    cudaGetSymbolAddress((void**)&b4h, g_b4hi);
    cudaGetSymbolAddress((void**)&b4l, g_b4lo);

    cudaFuncSetAttribute(hgemm<0>, cudaFuncAttributeMaxDynamicSharedMemorySize, 65536);
    cudaFuncSetAttribute(hgemm<1>, cudaFuncAttributeMaxDynamicSharedMemorySize, 65536);

    // operand conversions (weights + input)
    convA<<<(LSEQ * DM + 255) / 256, 256>>>(x, a1h, a1l, LSEQ * DM);
    convBT<<<dim3(DM / 32, (2 * DI) / 32), 256>>>(in_proj_w, b1h, b1l, DM, 2 * DI);
    convBT<<<dim3(2, DI / 32), 256>>>(dt_proj_w, b3h, b3l, RK, DI);
    convBT<<<dim3(DI / 32, DM / 32), 256>>>(out_proj_w, b4h, b4l, DI, DM);

    // GEMM1: [2048,768]@[768,3072] -> g_xr
    hgemm<0><<<dim3((2 * DI) / 128, LSEQ / 128, 1), 256, 65536>>>(
        a1h, a1l, b1h, b1l, xr, LSEQ, 2 * DI, DM, nullptr);

    // conv + silu -> u
    conv_silu_kernel<<<(LSEQ * DI) / 256, 256>>>(conv_w, conv_b);

    // GEMM2 (split-K x8): u[2048,1536]@x_proj_w[1536,80] -> partials -> xdbl
    sgemm<0><<<dim3(1, LSEQ / 128, KSPL), 256>>>(u, x_proj_w, x2p, LSEQ, 80, DI, DI, 80, 80, nullptr);
    reduce_splitk<<<(LSEQ * 80 + 255) / 256, 256>>>(x2p, xdbl, LSEQ * 80);

    // GEMM3 via tensor cores: xdbl[:,:48]@dt_proj_w[48,1536] + softplus -> delta
    convA_strided<<<(LSEQ * RK + 255) / 256, 256>>>(xdbl, a3h, a3l, LSEQ, RK, 80);
    hgemm<1><<<dim3(DI / 128, LSEQ / 128, 1), 256, 65536>>>(
        a3h, a3l, b3h, b3l, delta, LSEQ, DI, RK, dt_proj_b);

    // selective scan
    scan_phase1<<<dim3(DI / 256, NCH), 256>>>(a_log);
    scan_phase2<<<(DI * DS) / 256, 256>>>(a_log);
    scan_phase3<<<dim3(DI / 256, NCH), 256>>>(a_log, d_param);

    // GEMM4 (split-K x3): y[2048,1536]@out_proj_w[1536,768] -> partials -> out
    hgemm<0><<<dim3(DM / 128, LSEQ / 128, Z4), 256, 65536>>>(
        a4h, a4l, b4h, b4l, o4p, LSEQ, DM, DI, nullptr);
    reduceN<Z4><<<(LSEQ * DM / 4 + 255) / 256, 256>>>(o4p, out, LSEQ * DM / 4);
}